// round 4
// baseline (speedup 1.0000x reference)
#include <cuda_runtime.h>
#include <cstdint>
#include <cstddef>

// Problem dims
#define VN 128
#define HN 512
#define BN 512
#define SN 256
#define KC 16   // K-chunk per smem stage

// Static scratch (module-load allocated; no runtime allocation)
__device__ float g_hs_f[(size_t)(SN + 1) * BN * HN];  // forward h history, slot 0 = h0 (zeros)
__device__ float g_hs_b[(size_t)(SN + 1) * BN * HN];  // backward-scan h history
__device__ float g_c[2 * BN * HN];                    // cell state, [dir][b][j]

__device__ __forceinline__ float to_tf32(float x) {
    float r;
    asm("cvt.rna.tf32.f32 %0, %1;" : "=f"(r) : "f"(x));
    return r;
}

__device__ __forceinline__ float4 cvt4(float4 v) {
    return make_float4(to_tf32(v.x), to_tf32(v.y), to_tf32(v.z), to_tf32(v.w));
}

__device__ __forceinline__ void mma_tf32(float* d, const unsigned* a, const unsigned* b) {
    asm volatile(
        "mma.sync.aligned.m16n8k8.row.col.f32.tf32.tf32.f32 "
        "{%0,%1,%2,%3}, {%4,%5,%6,%7}, {%8,%9}, {%0,%1,%2,%3};\n"
        : "+f"(d[0]), "+f"(d[1]), "+f"(d[2]), "+f"(d[3])
        : "r"(a[0]), "r"(a[1]), "r"(a[2]), "r"(a[3]),
          "r"(b[0]), "r"(b[1]));
}

__device__ __forceinline__ float sigmf(float x) { return 1.0f / (1.0f + expf(-x)); }

// Store one staged K-chunk (reg -> smem). Row stride 20 floats (pad 4) => conflict-free frags.
__device__ __forceinline__ void sts_chunk(float* As, float* Bs, int lrow, int lhalf,
                                          float4 ra0, float4 ra1, float4 rb0, float4 rb1) {
    *(float4*)(As + lrow * 20 + lhalf * 8)     = ra0;
    *(float4*)(As + lrow * 20 + lhalf * 8 + 4) = ra1;
    *(float4*)(Bs + lrow * 20 + lhalf * 8)     = rb0;
    *(float4*)(Bs + lrow * 20 + lhalf * 8 + 4) = rb1;
}

// 16 m16n8k8 MMAs x 2 k-steps over the staged KC=16 chunk. Warp tile 64x32.
__device__ __forceinline__ void compute_chunk(const float* As, const float* Bs,
                                              int wm, int wn, int gr, int q,
                                              float acc[4][4][4]) {
#pragma unroll
    for (int ks = 0; ks < 2; ks++) {
        const int kk = ks * 8;
        unsigned af[4][4], bf[4][2];
#pragma unroll
        for (int tm = 0; tm < 4; tm++) {
            int r = wm * 64 + tm * 16 + gr;
            int c = kk + q;
            af[tm][0] = __float_as_uint(As[r * 20 + c]);
            af[tm][1] = __float_as_uint(As[(r + 8) * 20 + c]);
            af[tm][2] = __float_as_uint(As[r * 20 + c + 4]);
            af[tm][3] = __float_as_uint(As[(r + 8) * 20 + c + 4]);
        }
#pragma unroll
        for (int tn = 0; tn < 4; tn++) {
            int n = wn * 32 + tn * 8 + gr;
            bf[tn][0] = __float_as_uint(Bs[n * 20 + kk + q]);
            bf[tn][1] = __float_as_uint(Bs[n * 20 + kk + q + 4]);
        }
#pragma unroll
        for (int tm = 0; tm < 4; tm++)
#pragma unroll
            for (int tn = 0; tn < 4; tn++)
                mma_tf32(acc[tm][tn], af[tm], bf[tn]);
    }
}

__global__ void init_kernel() {
    int i = blockIdx.x * blockDim.x + threadIdx.x;
    if (i < BN * HN) { g_hs_f[i] = 0.f; g_hs_b[i] = 0.f; }
    if (i < 2 * BN * HN) g_c[i] = 0.f;
}

// One recurrence step, both directions (blockIdx.z). CTA tile: 128 batch rows x 32 neurons
// (x 4 gates = 128 GEMM columns), K = 640 = 512 (h_prev) + 128 (one-hot x_t folded in).
__global__ __launch_bounds__(256) void step_kernel(
    int t, const int* __restrict__ x,
    const float* __restrict__ Wx_f, const float* __restrict__ Wh_f,
    const float* __restrict__ bx_f, const float* __restrict__ bh_f,
    const float* __restrict__ Wx_b, const float* __restrict__ Wh_b,
    const float* __restrict__ bx_b, const float* __restrict__ bh_b) {
    __shared__ __align__(16) float As[128 * 20];
    __shared__ __align__(16) float Bs[128 * 20];
    __shared__ float bsum[128];

    const int tid = threadIdx.x;
    const int d = blockIdx.z;
    const int b0 = blockIdx.x * 128;
    const int j0 = blockIdx.y * 32;
    const int t_eff = d ? (SN - 1 - t) : t;

    const float* __restrict__ Wx  = d ? Wx_b : Wx_f;
    const float* __restrict__ Wh  = d ? Wh_b : Wh_f;
    const float* __restrict__ bxp = d ? bx_b : bx_f;
    const float* __restrict__ bhp = d ? bh_b : bh_f;
    float* hs = d ? g_hs_b : g_hs_f;
    float* cst = g_c + (size_t)d * BN * HN;
    const float* hprev = hs + (size_t)t * BN * HN;
    float* hout = hs + (size_t)(t + 1) * BN * HN;

    if (tid < 128) {
        int jj = tid >> 2, gate = tid & 3, j = j0 + jj;
        bsum[tid] = bxp[gate * HN + j] + bhp[gate * HN + j];
    }

    const int lrow = tid >> 1;   // 0..127 (loader row)
    const int lhalf = tid & 1;   // which 8-float half of the 16-wide chunk
    const int warp = tid >> 5, lane = tid & 31;
    const int wm = warp >> 2, wn = warp & 3;
    const int gr = lane >> 2, q = lane & 3;

    // B row n -> (neuron jj, gate): n = jj*4 + gate so each lane-pair owns all 4 gates of a cell
    const int jjB = lrow >> 2, gateB = lrow & 3, jB = j0 + jjB;
    const float* whRow = Wh + ((size_t)gateB * HN + jB) * HN;
    const float* wxRow = Wx + ((size_t)gateB * HN + jB) * VN;
    const float* aRow  = hprev + (size_t)(b0 + lrow) * HN;
    const int xv = x[(b0 + lrow) * SN + t_eff];

    float acc[4][4][4];
#pragma unroll
    for (int i = 0; i < 4; i++)
#pragma unroll
        for (int jx = 0; jx < 4; jx++)
#pragma unroll
            for (int kx = 0; kx < 4; kx++) acc[i][jx][kx] = 0.f;

    float4 ra0, ra1, rb0, rb1;

    // --- chunk loaders (global -> regs, tf32-converted) ---
#define LOAD_CHUNK(kc)                                                           \
    {                                                                            \
        int k = (kc) * KC + lhalf * 8;                                           \
        if (k < 512) {                                                           \
            ra0 = cvt4(*(const float4*)(aRow + k));                              \
            ra1 = cvt4(*(const float4*)(aRow + k + 4));                          \
        } else {                                                                 \
            int kk = k - 512;                                                    \
            ra0 = make_float4(xv == kk + 0 ? 1.f : 0.f, xv == kk + 1 ? 1.f : 0.f,\
                              xv == kk + 2 ? 1.f : 0.f, xv == kk + 3 ? 1.f : 0.f);\
            ra1 = make_float4(xv == kk + 4 ? 1.f : 0.f, xv == kk + 5 ? 1.f : 0.f,\
                              xv == kk + 6 ? 1.f : 0.f, xv == kk + 7 ? 1.f : 0.f);\
        }                                                                        \
        const float* srcB = (k < 512) ? (whRow + k) : (wxRow + (k - 512));       \
        rb0 = cvt4(*(const float4*)(srcB));                                      \
        rb1 = cvt4(*(const float4*)(srcB + 4));                                  \
    }

    LOAD_CHUNK(0);
    sts_chunk(As, Bs, lrow, lhalf, ra0, ra1, rb0, rb1);
    __syncthreads();

    const int NK = 640 / KC;  // 40
    for (int kc = 0; kc < NK; kc++) {
        bool more = (kc + 1 < NK);
        if (more) LOAD_CHUNK(kc + 1);
        compute_chunk(As, Bs, wm, wn, gr, q, acc);
        __syncthreads();
        if (more) {
            sts_chunk(As, Bs, lrow, lhalf, ra0, ra1, rb0, rb1);
            __syncthreads();
        }
    }
#undef LOAD_CHUNK

    // --- epilogue: gates + cell update. Lane pair (l, l^1) exchanges to gather all 4 gates. ---
#pragma unroll
    for (int tm = 0; tm < 4; tm++) {
        int rbase = b0 + wm * 64 + tm * 16 + gr;
#pragma unroll
        for (int tn = 0; tn < 4; tn++) {
            float c0 = acc[tm][tn][0], c1 = acc[tm][tn][1];
            float c2 = acc[tm][tn][2], c3 = acc[tm][tn][3];
            float e0 = __shfl_xor_sync(0xffffffffu, c0, 1);
            float e1 = __shfl_xor_sync(0xffffffffu, c1, 1);
            float e2 = __shfl_xor_sync(0xffffffffu, c2, 1);
            float e3 = __shfl_xor_sync(0xffffffffu, c3, 1);
            float iv, fv, ov, gv;
            int brow;
            if ((q & 1) == 0) { iv = c0; fv = c1; ov = e0; gv = e1; brow = rbase; }
            else              { iv = e2; fv = e3; ov = c2; gv = c3; brow = rbase + 8; }
            int jj4 = wn * 32 + tn * 8 + (q >> 1) * 4;
            float4 bs = *(const float4*)&bsum[jj4];
            float gi = sigmf(iv + bs.x);
            float gf = sigmf(fv + bs.y);
            float go = sigmf(ov + bs.z);
            float gg = tanhf(gv + bs.w);
            size_t ci = (size_t)brow * HN + (size_t)(j0 + (jj4 >> 2));
            float cn = gf * cst[ci] + gi * gg;
            cst[ci] = cn;
            hout[ci] = go * tanhf(cn);
        }
    }
}

// Final FC: y[b,s,v] = [hf(s) | hb(s)] . Wfc[v,:] + bfc[v].  M = S*B, N = V = 128, K = 1024.
__global__ __launch_bounds__(256) void fc_kernel(const float* __restrict__ Wfc,
                                                 const float* __restrict__ bfc,
                                                 float* __restrict__ y) {
    __shared__ __align__(16) float As[128 * 20];
    __shared__ __align__(16) float Bs[128 * 20];
    __shared__ float bsh[128];

    const int tid = threadIdx.x;
    const int mt = blockIdx.x;       // 1024 CTAs: 256 s values x 4 batch tiles
    const int s = mt >> 2;
    const int b0 = (mt & 3) * 128;

    const float* Af = g_hs_f + (size_t)(s + 1) * BN * HN;   // hf[s]
    const float* Ab = g_hs_b + (size_t)(SN - s) * BN * HN;  // hb[s] (un-reversed)

    if (tid < 128) bsh[tid] = bfc[tid];

    const int lrow = tid >> 1, lhalf = tid & 1;
    const int warp = tid >> 5, lane = tid & 31;
    const int wm = warp >> 2, wn = warp & 3;
    const int gr = lane >> 2, q = lane & 3;

    const float* afRow = Af + (size_t)(b0 + lrow) * HN;
    const float* abRow = Ab + (size_t)(b0 + lrow) * HN;
    const float* bRow = Wfc + (size_t)lrow * (2 * HN);

    float acc[4][4][4];
#pragma unroll
    for (int i = 0; i < 4; i++)
#pragma unroll
        for (int jx = 0; jx < 4; jx++)
#pragma unroll
            for (int kx = 0; kx < 4; kx++) acc[i][jx][kx] = 0.f;

    float4 ra0, ra1, rb0, rb1;

#define LOAD_CHUNK_FC(kc)                                                   \
    {                                                                       \
        int k = (kc) * KC + lhalf * 8;                                      \
        const float* srcA = (k < 512) ? (afRow + k) : (abRow + (k - 512));  \
        ra0 = cvt4(*(const float4*)(srcA));                                 \
        ra1 = cvt4(*(const float4*)(srcA + 4));                             \
        rb0 = cvt4(*(const float4*)(bRow + k));                             \
        rb1 = cvt4(*(const float4*)(bRow + k + 4));                         \
    }

    LOAD_CHUNK_FC(0);
    sts_chunk(As, Bs, lrow, lhalf, ra0, ra1, rb0, rb1);
    __syncthreads();

    const int NK = 1024 / KC;  // 64
    for (int kc = 0; kc < NK; kc++) {
        bool more = (kc + 1 < NK);
        if (more) LOAD_CHUNK_FC(kc + 1);
        compute_chunk(As, Bs, wm, wn, gr, q, acc);
        __syncthreads();
        if (more) {
            sts_chunk(As, Bs, lrow, lhalf, ra0, ra1, rb0, rb1);
            __syncthreads();
        }
    }
#undef LOAD_CHUNK_FC

#pragma unroll
    for (int tm = 0; tm < 4; tm++) {
        int b = b0 + wm * 64 + tm * 16 + gr;
#pragma unroll
        for (int tn = 0; tn < 4; tn++) {
            int n0 = wn * 32 + tn * 8 + 2 * q;
            float2 w0 = make_float2(acc[tm][tn][0] + bsh[n0], acc[tm][tn][1] + bsh[n0 + 1]);
            *(float2*)(y + ((size_t)b * SN + s) * VN + n0) = w0;
            float2 w1 = make_float2(acc[tm][tn][2] + bsh[n0], acc[tm][tn][3] + bsh[n0 + 1]);
            *(float2*)(y + ((size_t)(b + 8) * SN + s) * VN + n0) = w1;
        }
    }
}

extern "C" void kernel_launch(void* const* d_in, const int* in_sizes, int n_in,
                              void* d_out, int out_size) {
    const int*   x    = (const int*)d_in[0];
    const float* Wx_f = (const float*)d_in[1];
    const float* Wh_f = (const float*)d_in[2];
    const float* bx_f = (const float*)d_in[3];
    const float* bh_f = (const float*)d_in[4];
    const float* Wx_b = (const float*)d_in[5];
    const float* Wh_b = (const float*)d_in[6];
    const float* bx_b = (const float*)d_in[7];
    const float* bh_b = (const float*)d_in[8];
    const float* Wfc  = (const float*)d_in[9];
    const float* bfc  = (const float*)d_in[10];
    float* y = (float*)d_out;

    // zero h0 / c0 state
    init_kernel<<<2048, 256>>>();

    // 256 sequential recurrence steps; both directions fused per launch.
    dim3 g(4, 16, 2);  // 4 batch tiles x 16 neuron tiles x 2 directions = 128 CTAs
    for (int t = 0; t < SN; t++)
        step_kernel<<<g, 256>>>(t, x, Wx_f, Wh_f, bx_f, bh_f, Wx_b, Wh_b, bx_b, bh_b);

    // final projection over all (s, b)
    fc_kernel<<<1024, 256>>>(Wfc, bfc, y);
}

// round 5
// speedup vs baseline: 1.0043x; 1.0043x over previous
#include <cuda_runtime.h>
#include <cstdint>
#include <cstddef>

// Problem dims
#define VN 128
#define HN 512
#define BN 512
#define SN 256
#define KC 16   // K-chunk per smem stage

// Static scratch (module-load allocated; no runtime allocation)
__device__ float g_hs_f[(size_t)(SN + 1) * BN * HN];  // forward h history, slot 0 = h0 (zeros)
__device__ float g_hs_b[(size_t)(SN + 1) * BN * HN];  // backward-scan h history
__device__ float g_c[2 * BN * HN];                    // cell state, [dir][b][j]

__device__ __forceinline__ float to_tf32(float x) {
    float r;
    asm("cvt.rna.tf32.f32 %0, %1;" : "=f"(r) : "f"(x));
    return r;
}

__device__ __forceinline__ float4 cvt4(float4 v) {
    return make_float4(to_tf32(v.x), to_tf32(v.y), to_tf32(v.z), to_tf32(v.w));
}

__device__ __forceinline__ void mma_tf32(float* d, const unsigned* a, const unsigned* b) {
    asm volatile(
        "mma.sync.aligned.m16n8k8.row.col.f32.tf32.tf32.f32 "
        "{%0,%1,%2,%3}, {%4,%5,%6,%7}, {%8,%9}, {%0,%1,%2,%3};\n"
        : "+f"(d[0]), "+f"(d[1]), "+f"(d[2]), "+f"(d[3])
        : "r"(a[0]), "r"(a[1]), "r"(a[2]), "r"(a[3]),
          "r"(b[0]), "r"(b[1]));
}

__device__ __forceinline__ float sigmf(float x) { return 1.0f / (1.0f + expf(-x)); }

// Store one staged K-chunk (reg -> smem). Row stride 20 floats (pad 4) => conflict-free frags.
__device__ __forceinline__ void sts_chunk(float* As, float* Bs, int lrow, int lhalf,
                                          float4 ra0, float4 ra1, float4 rb0, float4 rb1) {
    *(float4*)(As + lrow * 20 + lhalf * 8)     = ra0;
    *(float4*)(As + lrow * 20 + lhalf * 8 + 4) = ra1;
    *(float4*)(Bs + lrow * 20 + lhalf * 8)     = rb0;
    *(float4*)(Bs + lrow * 20 + lhalf * 8 + 4) = rb1;
}

// 16 m16n8k8 MMAs x 2 k-steps over the staged KC=16 chunk. Warp tile 64x32.
__device__ __forceinline__ void compute_chunk(const float* As, const float* Bs,
                                              int wm, int wn, int gr, int q,
                                              float acc[4][4][4]) {
#pragma unroll
    for (int ks = 0; ks < 2; ks++) {
        const int kk = ks * 8;
        unsigned af[4][4], bf[4][2];
#pragma unroll
        for (int tm = 0; tm < 4; tm++) {
            int r = wm * 64 + tm * 16 + gr;
            int c = kk + q;
            af[tm][0] = __float_as_uint(As[r * 20 + c]);
            af[tm][1] = __float_as_uint(As[(r + 8) * 20 + c]);
            af[tm][2] = __float_as_uint(As[r * 20 + c + 4]);
            af[tm][3] = __float_as_uint(As[(r + 8) * 20 + c + 4]);
        }
#pragma unroll
        for (int tn = 0; tn < 4; tn++) {
            int n = wn * 32 + tn * 8 + gr;
            bf[tn][0] = __float_as_uint(Bs[n * 20 + kk + q]);
            bf[tn][1] = __float_as_uint(Bs[n * 20 + kk + q + 4]);
        }
#pragma unroll
        for (int tm = 0; tm < 4; tm++)
#pragma unroll
            for (int tn = 0; tn < 4; tn++)
                mma_tf32(acc[tm][tn], af[tm], bf[tn]);
    }
}

__global__ void init_kernel() {
    int i = blockIdx.x * blockDim.x + threadIdx.x;
    if (i < BN * HN) { g_hs_f[i] = 0.f; g_hs_b[i] = 0.f; }
    if (i < 2 * BN * HN) g_c[i] = 0.f;
}

// One recurrence step, both directions (blockIdx.z). CTA tile: 128 batch rows x 32 neurons
// (x 4 gates = 128 GEMM columns), K = 640 = 512 (h_prev) + 128 (one-hot x_t folded in).
__global__ __launch_bounds__(256) void step_kernel(
    int t, const int* __restrict__ x,
    const float* __restrict__ Wx_f, const float* __restrict__ Wh_f,
    const float* __restrict__ bx_f, const float* __restrict__ bh_f,
    const float* __restrict__ Wx_b, const float* __restrict__ Wh_b,
    const float* __restrict__ bx_b, const float* __restrict__ bh_b) {
    __shared__ __align__(16) float As[128 * 20];
    __shared__ __align__(16) float Bs[128 * 20];
    __shared__ float bsum[128];

    const int tid = threadIdx.x;
    const int d = blockIdx.z;
    const int b0 = blockIdx.x * 128;
    const int j0 = blockIdx.y * 32;
    const int t_eff = d ? (SN - 1 - t) : t;

    const float* __restrict__ Wx  = d ? Wx_b : Wx_f;
    const float* __restrict__ Wh  = d ? Wh_b : Wh_f;
    const float* __restrict__ bxp = d ? bx_b : bx_f;
    const float* __restrict__ bhp = d ? bh_b : bh_f;
    float* hs = d ? g_hs_b : g_hs_f;
    float* cst = g_c + (size_t)d * BN * HN;
    const float* hprev = hs + (size_t)t * BN * HN;
    float* hout = hs + (size_t)(t + 1) * BN * HN;

    if (tid < 128) {
        int jj = tid >> 2, gate = tid & 3, j = j0 + jj;
        bsum[tid] = bxp[gate * HN + j] + bhp[gate * HN + j];
    }

    const int lrow = tid >> 1;   // 0..127 (loader row)
    const int lhalf = tid & 1;   // which 8-float half of the 16-wide chunk
    const int warp = tid >> 5, lane = tid & 31;
    const int wm = warp >> 2, wn = warp & 3;
    const int gr = lane >> 2, q = lane & 3;

    // B row n -> (neuron jj, gate): n = jj*4 + gate so each lane-pair owns all 4 gates of a cell
    const int jjB = lrow >> 2, gateB = lrow & 3, jB = j0 + jjB;
    const float* whRow = Wh + ((size_t)gateB * HN + jB) * HN;
    const float* wxRow = Wx + ((size_t)gateB * HN + jB) * VN;
    const float* aRow  = hprev + (size_t)(b0 + lrow) * HN;
    const int xv = x[(b0 + lrow) * SN + t_eff];

    float acc[4][4][4];
#pragma unroll
    for (int i = 0; i < 4; i++)
#pragma unroll
        for (int jx = 0; jx < 4; jx++)
#pragma unroll
            for (int kx = 0; kx < 4; kx++) acc[i][jx][kx] = 0.f;

    float4 ra0, ra1, rb0, rb1;

    // --- chunk loaders (global -> regs, tf32-converted) ---
#define LOAD_CHUNK(kc)                                                           \
    {                                                                            \
        int k = (kc) * KC + lhalf * 8;                                           \
        if (k < 512) {                                                           \
            ra0 = cvt4(*(const float4*)(aRow + k));                              \
            ra1 = cvt4(*(const float4*)(aRow + k + 4));                          \
        } else {                                                                 \
            int kk = k - 512;                                                    \
            ra0 = make_float4(xv == kk + 0 ? 1.f : 0.f, xv == kk + 1 ? 1.f : 0.f,\
                              xv == kk + 2 ? 1.f : 0.f, xv == kk + 3 ? 1.f : 0.f);\
            ra1 = make_float4(xv == kk + 4 ? 1.f : 0.f, xv == kk + 5 ? 1.f : 0.f,\
                              xv == kk + 6 ? 1.f : 0.f, xv == kk + 7 ? 1.f : 0.f);\
        }                                                                        \
        const float* srcB = (k < 512) ? (whRow + k) : (wxRow + (k - 512));       \
        rb0 = cvt4(*(const float4*)(srcB));                                      \
        rb1 = cvt4(*(const float4*)(srcB + 4));                                  \
    }

    LOAD_CHUNK(0);
    sts_chunk(As, Bs, lrow, lhalf, ra0, ra1, rb0, rb1);
    __syncthreads();

    const int NK = 640 / KC;  // 40
    for (int kc = 0; kc < NK; kc++) {
        bool more = (kc + 1 < NK);
        if (more) LOAD_CHUNK(kc + 1);
        compute_chunk(As, Bs, wm, wn, gr, q, acc);
        __syncthreads();
        if (more) {
            sts_chunk(As, Bs, lrow, lhalf, ra0, ra1, rb0, rb1);
            __syncthreads();
        }
    }
#undef LOAD_CHUNK

    // --- epilogue: gates + cell update. Lane pair (l, l^1) exchanges to gather all 4 gates. ---
#pragma unroll
    for (int tm = 0; tm < 4; tm++) {
        int rbase = b0 + wm * 64 + tm * 16 + gr;
#pragma unroll
        for (int tn = 0; tn < 4; tn++) {
            float c0 = acc[tm][tn][0], c1 = acc[tm][tn][1];
            float c2 = acc[tm][tn][2], c3 = acc[tm][tn][3];
            float e0 = __shfl_xor_sync(0xffffffffu, c0, 1);
            float e1 = __shfl_xor_sync(0xffffffffu, c1, 1);
            float e2 = __shfl_xor_sync(0xffffffffu, c2, 1);
            float e3 = __shfl_xor_sync(0xffffffffu, c3, 1);
            float iv, fv, ov, gv;
            int brow;
            if ((q & 1) == 0) { iv = c0; fv = c1; ov = e0; gv = e1; brow = rbase; }
            else              { iv = e2; fv = e3; ov = c2; gv = c3; brow = rbase + 8; }
            int jj4 = wn * 32 + tn * 8 + (q >> 1) * 4;
            float4 bs = *(const float4*)&bsum[jj4];
            float gi = sigmf(iv + bs.x);
            float gf = sigmf(fv + bs.y);
            float go = sigmf(ov + bs.z);
            float gg = tanhf(gv + bs.w);
            size_t ci = (size_t)brow * HN + (size_t)(j0 + (jj4 >> 2));
            float cn = gf * cst[ci] + gi * gg;
            cst[ci] = cn;
            hout[ci] = go * tanhf(cn);
        }
    }
}

// Final FC: y[b,s,v] = [hf(s) | hb(s)] . Wfc[v,:] + bfc[v].  M = S*B, N = V = 128, K = 1024.
__global__ __launch_bounds__(256) void fc_kernel(const float* __restrict__ Wfc,
                                                 const float* __restrict__ bfc,
                                                 float* __restrict__ y) {
    __shared__ __align__(16) float As[128 * 20];
    __shared__ __align__(16) float Bs[128 * 20];
    __shared__ float bsh[128];

    const int tid = threadIdx.x;
    const int mt = blockIdx.x;       // 1024 CTAs: 256 s values x 4 batch tiles
    const int s = mt >> 2;
    const int b0 = (mt & 3) * 128;

    const float* Af = g_hs_f + (size_t)(s + 1) * BN * HN;   // hf[s]
    const float* Ab = g_hs_b + (size_t)(SN - s) * BN * HN;  // hb[s] (un-reversed)

    if (tid < 128) bsh[tid] = bfc[tid];

    const int lrow = tid >> 1, lhalf = tid & 1;
    const int warp = tid >> 5, lane = tid & 31;
    const int wm = warp >> 2, wn = warp & 3;
    const int gr = lane >> 2, q = lane & 3;

    const float* afRow = Af + (size_t)(b0 + lrow) * HN;
    const float* abRow = Ab + (size_t)(b0 + lrow) * HN;
    const float* bRow = Wfc + (size_t)lrow * (2 * HN);

    float acc[4][4][4];
#pragma unroll
    for (int i = 0; i < 4; i++)
#pragma unroll
        for (int jx = 0; jx < 4; jx++)
#pragma unroll
            for (int kx = 0; kx < 4; kx++) acc[i][jx][kx] = 0.f;

    float4 ra0, ra1, rb0, rb1;

#define LOAD_CHUNK_FC(kc)                                                   \
    {                                                                       \
        int k = (kc) * KC + lhalf * 8;                                      \
        const float* srcA = (k < 512) ? (afRow + k) : (abRow + (k - 512));  \
        ra0 = cvt4(*(const float4*)(srcA));                                 \
        ra1 = cvt4(*(const float4*)(srcA + 4));                             \
        rb0 = cvt4(*(const float4*)(bRow + k));                             \
        rb1 = cvt4(*(const float4*)(bRow + k + 4));                         \
    }

    LOAD_CHUNK_FC(0);
    sts_chunk(As, Bs, lrow, lhalf, ra0, ra1, rb0, rb1);
    __syncthreads();

    const int NK = 1024 / KC;  // 64
    for (int kc = 0; kc < NK; kc++) {
        bool more = (kc + 1 < NK);
        if (more) LOAD_CHUNK_FC(kc + 1);
        compute_chunk(As, Bs, wm, wn, gr, q, acc);
        __syncthreads();
        if (more) {
            sts_chunk(As, Bs, lrow, lhalf, ra0, ra1, rb0, rb1);
            __syncthreads();
        }
    }
#undef LOAD_CHUNK_FC

#pragma unroll
    for (int tm = 0; tm < 4; tm++) {
        int b = b0 + wm * 64 + tm * 16 + gr;
#pragma unroll
        for (int tn = 0; tn < 4; tn++) {
            int n0 = wn * 32 + tn * 8 + 2 * q;
            float2 w0 = make_float2(acc[tm][tn][0] + bsh[n0], acc[tm][tn][1] + bsh[n0 + 1]);
            *(float2*)(y + ((size_t)b * SN + s) * VN + n0) = w0;
            float2 w1 = make_float2(acc[tm][tn][2] + bsh[n0], acc[tm][tn][3] + bsh[n0 + 1]);
            *(float2*)(y + ((size_t)(b + 8) * SN + s) * VN + n0) = w1;
        }
    }
}

extern "C" void kernel_launch(void* const* d_in, const int* in_sizes, int n_in,
                              void* d_out, int out_size) {
    const int*   x    = (const int*)d_in[0];
    const float* Wx_f = (const float*)d_in[1];
    const float* Wh_f = (const float*)d_in[2];
    const float* bx_f = (const float*)d_in[3];
    const float* bh_f = (const float*)d_in[4];
    const float* Wx_b = (const float*)d_in[5];
    const float* Wh_b = (const float*)d_in[6];
    const float* bx_b = (const float*)d_in[7];
    const float* bh_b = (const float*)d_in[8];
    const float* Wfc  = (const float*)d_in[9];
    const float* bfc  = (const float*)d_in[10];
    float* y = (float*)d_out;

    // zero h0 / c0 state
    init_kernel<<<2048, 256>>>();

    // 256 sequential recurrence steps; both directions fused per launch.
    dim3 g(4, 16, 2);  // 4 batch tiles x 16 neuron tiles x 2 directions = 128 CTAs
    for (int t = 0; t < SN; t++)
        step_kernel<<<g, 256>>>(t, x, Wx_f, Wh_f, bx_f, bh_f, Wx_b, Wh_b, bx_b, bh_b);

    // final projection over all (s, b)
    fc_kernel<<<1024, 256>>>(Wfc, bfc, y);
}